// round 14
// baseline (speedup 1.0000x reference)
#include <cuda_runtime.h>
#include <math.h>

#define BATCH 64
#define NTOT  65536
#define DIM   1024
#define CHUNK 128
#define MAX_CHUNKS 576    // NTOT/CHUNK + BATCH
#define NSPLIT 16

// ---------------- device scratch (static, no allocation) ----------------
__device__ float  g_vpart[NSPLIT * BATCH * DIM];
__device__ float  g_v[BATCH * DIM];
__device__ int    g_chunk_seg[MAX_CHUNKS];
__device__ int    g_chunk_start[MAX_CHUNKS];
__device__ int    g_chunk_cnt[MAX_CHUNKS];
__device__ int    g_seg_chunk_start[BATCH];
__device__ int    g_seg_chunk_cnt[BATCH];
__device__ float  g_part_m[MAX_CHUNKS];
__device__ float  g_part_z[MAX_CHUNKS];
__device__ float4 g_part_acc[MAX_CHUNKS * (DIM / 4)];
__device__ int    g_tile_done[NSPLIT];   // split-K arrivals; self-cleaning
__device__ int    g_seg_done[BATCH];     // per-segment chunk arrivals; self-cleaning

// packed f32x2 helpers (sm_103a FFMA2 — PTX-only)
#define FMA2(d, a, b, c) \
    asm("fma.rn.f32x2 %0, %1, %2, %3;" : "=l"(d) : "l"(a), "l"(b), "l"(c))
#define PACK2(out, lo, hi) \
    asm("mov.b64 %0, {%1, %2};" : "=l"(out) : "f"(lo), "f"(hi))

// ============ K1: v-projection (f32x2) + split-K reduce + setup ============
// grid (4 m-tiles, 4 b-tiles, 16 h-splits) = 256 blocks, 256 threads.
__global__ void k1_vproj_setup(const float* __restrict__ dstate,
                               const float* __restrict__ W,
                               const int* __restrict__ lens_raw) {
    __shared__ unsigned long long dsh2[8][64];   // 16 b's packed into 8 f32x2, 64 h
    int m  = blockIdx.x * 256 + threadIdx.x;
    int b0 = blockIdx.y * 16;
    int h0 = blockIdx.z * 64;

    for (int i = threadIdx.x; i < 8 * 64; i += 256) {
        int p = i >> 6, hh = i & 63;
        float lo = dstate[(b0 + 2 * p)     * DIM + h0 + hh];
        float hi = dstate[(b0 + 2 * p + 1) * DIM + h0 + hh];
        unsigned long long pk; PACK2(pk, lo, hi);
        dsh2[p][hh] = pk;
    }
    __syncthreads();

    unsigned long long acc2[8];
#pragma unroll
    for (int i = 0; i < 8; i++) acc2[i] = 0ull;

#pragma unroll 4
    for (int hh = 0; hh < 64; hh++) {
        float w = W[(size_t)(h0 + hh) * DIM + m];
        unsigned long long w2; PACK2(w2, w, w);
#pragma unroll
        for (int i = 0; i < 8; i++) FMA2(acc2[i], dsh2[i][hh], w2, acc2[i]);
    }

    float* outp = g_vpart + (size_t)blockIdx.z * (BATCH * DIM);
#pragma unroll
    for (int i = 0; i < 8; i++) {
        unsigned long long a = acc2[i];
        outp[(b0 + 2 * i)     * DIM + m] = __int_as_float((int)(a & 0xffffffffull));
        outp[(b0 + 2 * i + 1) * DIM + m] = __int_as_float((int)(a >> 32));
    }

    // ---- last z-split for this (bx,by) tile reduces the 16 partials ----
    __shared__ int s_last;
    __threadfence();
    __syncthreads();
    if (threadIdx.x == 0)
        s_last = (atomicAdd(&g_tile_done[blockIdx.y * 4 + blockIdx.x], 1) == NSPLIT - 1) ? 1 : 0;
    __syncthreads();
    if (s_last) {
        __threadfence();   // acquire: make all splits' writes visible
        for (int i = threadIdx.x; i < 16 * 256; i += 256) {
            int bl = i >> 8, mm = i & 255;
            int b  = blockIdx.y * 16 + bl;
            int mc = blockIdx.x * 256 + mm;
            float s = 0.f;
#pragma unroll
            for (int p = 0; p < NSPLIT; p++)
                s += g_vpart[(size_t)p * BATCH * DIM + b * DIM + mc];
            g_v[b * DIM + mc] = s;
        }
        if (threadIdx.x == 0)
            g_tile_done[blockIdx.y * 4 + blockIdx.x] = 0;   // self-clean for replay
    }

    // ---- setup (chunk table) in block (0,0,0) — independent side task ----
    if (blockIdx.x == 0 && blockIdx.y == 0 && blockIdx.z == 0) {
        __shared__ int s_len[BATCH], s_noff[BATCH], s_coff[BATCH];
        int b = threadIdx.x;
        const long long* lens64 = (const long long*)lens_raw;
        bool is64 = (lens_raw[1] == 0);   // int64 LE: high word of elem0 is 0
        if (b < BATCH) s_len[b] = is64 ? (int)lens64[b] : lens_raw[b];
        __syncthreads();
        if (b == 0) {
            int noff = 0, coff = 0;
            for (int i = 0; i < BATCH; i++) {
                s_noff[i] = noff; s_coff[i] = coff;
                noff += s_len[i];
                coff += (s_len[i] + CHUNK - 1) / CHUNK;
            }
        }
        __syncthreads();
        if (b < BATCH) {
            int len = s_len[b];
            int nck = (len + CHUNK - 1) / CHUNK;
            int cs  = s_coff[b];
            g_seg_chunk_start[b] = cs;
            g_seg_chunk_cnt[b]   = nck;
            for (int k = 0; k < nck; k++) {
                g_chunk_seg[cs + k]   = b;
                g_chunk_start[cs + k] = s_noff[b] + k * CHUNK;
                int rem = len - k * CHUNK;
                g_chunk_cnt[cs + k]   = rem < CHUNK ? rem : CHUNK;
            }
        }
        // zero-fill table tail
        __syncthreads();
        int total = s_coff[BATCH - 1] + (s_len[BATCH - 1] + CHUNK - 1) / CHUNK;
        for (int c = total + threadIdx.x; c < MAX_CHUNKS; c += 256) g_chunk_cnt[c] = 0;
    }
}

// ============ K2: phase1 (one CTA = one chunk, 3 CTAs/SM) + last-arriver combine ============
__global__ void __launch_bounds__(256, 3) k2_phase1(const float* __restrict__ mem,
                                                    float* __restrict__ out) {
    __shared__ float4 s_acc[8][256];   // 32 KB per-warp accumulators
    __shared__ float4 s_v[256];        // 4 KB: segment v row (register diet)
    __shared__ float  s_m[8], s_z[8];
    __shared__ int    s_last;

    int c   = blockIdx.x;
    int cnt = g_chunk_cnt[c];
    if (cnt == 0) return;
    int seg   = g_chunk_seg[c];
    int start = g_chunk_start[c];
    int warp  = threadIdx.x >> 5;
    int lane  = threadIdx.x & 31;
    int t     = threadIdx.x;

    // stage this segment's v into shared (L2-hot)
    s_v[t] = ((const float4*)(g_v + seg * DIM))[t];
    __syncthreads();

    float m = -INFINITY, z = 0.f;
    float4 acc[8];
#pragma unroll
    for (int j = 0; j < 8; j++) acc[j] = make_float4(0.f, 0.f, 0.f, 0.f);

    for (int i = warp; i < cnt; i += 8) {
        const float4* row = (const float4*)(mem + (size_t)(start + i) * DIM);
        float4 r[8];
#pragma unroll
        for (int j = 0; j < 8; j++) r[j] = row[j * 32 + lane];   // batched LDG.128

        float s0 = 0.f, s1 = 0.f;
#pragma unroll
        for (int j = 0; j < 8; j += 2) {
            float4 v0 = s_v[j * 32 + lane];
            float4 v1 = s_v[(j + 1) * 32 + lane];
            s0 += r[j].x * v0.x + r[j].y * v0.y + r[j].z * v0.z + r[j].w * v0.w;
            s1 += r[j+1].x * v1.x + r[j+1].y * v1.y + r[j+1].z * v1.z + r[j+1].w * v1.w;
        }
        float s = s0 + s1;
#pragma unroll
        for (int o = 16; o > 0; o >>= 1) s += __shfl_xor_sync(0xffffffffu, s, o);

        if (s > m) {
            float sc = __expf(m - s);   // exp(-inf)=0 handles first node
            z = z * sc + 1.f;
#pragma unroll
            for (int j = 0; j < 8; j++) {
                acc[j].x = acc[j].x * sc + r[j].x;
                acc[j].y = acc[j].y * sc + r[j].y;
                acc[j].z = acc[j].z * sc + r[j].z;
                acc[j].w = acc[j].w * sc + r[j].w;
            }
            m = s;
        } else {
            float w8 = __expf(s - m);
            z += w8;
#pragma unroll
            for (int j = 0; j < 8; j++) {
                acc[j].x = fmaf(w8, r[j].x, acc[j].x);
                acc[j].y = fmaf(w8, r[j].y, acc[j].y);
                acc[j].z = fmaf(w8, r[j].z, acc[j].z);
                acc[j].w = fmaf(w8, r[j].w, acc[j].w);
            }
        }
    }

    // combine 8 warp-local accumulators -> chunk partial
#pragma unroll
    for (int j = 0; j < 8; j++) s_acc[warp][j * 32 + lane] = acc[j];
    if (lane == 0) { s_m[warp] = m; s_z[warp] = z; }
    __syncthreads();

    float m_b = -INFINITY;
#pragma unroll
    for (int w = 0; w < 8; w++) m_b = fmaxf(m_b, s_m[w]);

    float  z_b = 0.f;
    float4 a   = make_float4(0.f, 0.f, 0.f, 0.f);
#pragma unroll
    for (int w = 0; w < 8; w++) {
        float mw = s_m[w];
        float sc = (mw == -INFINITY) ? 0.f : __expf(mw - m_b);  // idle warp -> 0
        float4 aw = s_acc[w][t];
        a.x = fmaf(sc, aw.x, a.x);
        a.y = fmaf(sc, aw.y, a.y);
        a.z = fmaf(sc, aw.z, a.z);
        a.w = fmaf(sc, aw.w, a.w);
        z_b = fmaf(sc, s_z[w], z_b);
    }
    g_part_acc[c * (DIM / 4) + t] = a;
    if (t == 0) { g_part_m[c] = m_b; g_part_z[c] = z_b; }

    // ---- event-driven last-arriver: final combine for this segment ----
    __threadfence();
    __syncthreads();   // all partial writes visible before the arrival atomic
    if (t == 0)
        s_last = (atomicAdd(&g_seg_done[seg], 1) == g_seg_chunk_cnt[seg] - 1) ? 1 : 0;
    __syncthreads();
    if (s_last) {
        __threadfence();   // acquire: other chunks' partials now visible
        int cs = g_seg_chunk_start[seg];
        int cc = g_seg_chunk_cnt[seg];

        float m_g = -INFINITY;
        for (int ci = 0; ci < cc; ci++) m_g = fmaxf(m_g, g_part_m[cs + ci]);

        float  zg = 0.f;
        float4 ag = make_float4(0.f, 0.f, 0.f, 0.f);
        for (int ci = 0; ci < cc; ci++) {
            float sc = __expf(g_part_m[cs + ci] - m_g);
            float4 p = g_part_acc[(cs + ci) * (DIM / 4) + t];
            ag.x = fmaf(sc, p.x, ag.x);
            ag.y = fmaf(sc, p.y, ag.y);
            ag.z = fmaf(sc, p.z, ag.z);
            ag.w = fmaf(sc, p.w, ag.w);
            zg = fmaf(sc, g_part_z[cs + ci], zg);
        }
        float inv = 1.f / zg;
        ((float4*)out)[seg * (DIM / 4) + t] =
            make_float4(ag.x * inv, ag.y * inv, ag.z * inv, ag.w * inv);
        if (t == 0) g_seg_done[seg] = 0;   // self-clean for graph replay
    }
}

// ---------------- launch ----------------
extern "C" void kernel_launch(void* const* d_in, const int* in_sizes, int n_in,
                              void* d_out, int out_size) {
    // Identify inputs by element count (ordering-proof):
    //   memory_bank 67108864, decoder_state 65536, W 1048576, lens 64.
    const float* mem    = nullptr;
    const float* dstate = nullptr;
    const float* W      = nullptr;
    const int*   lens   = nullptr;
    for (int i = 0; i < n_in; i++) {
        switch (in_sizes[i]) {
            case 67108864: mem    = (const float*)d_in[i]; break;
            case 65536:    dstate = (const float*)d_in[i]; break;
            case 1048576:  W      = (const float*)d_in[i]; break;
            case 64:       lens   = (const int*)d_in[i];   break;
        }
    }
    float* out = (float*)d_out;

    k1_vproj_setup<<<dim3(4, 4, NSPLIT), 256>>>(dstate, W, lens);
    k2_phase1<<<MAX_CHUNKS, 256>>>(mem, out);
}

// round 15
// speedup vs baseline: 1.3536x; 1.3536x over previous
#include <cuda_runtime.h>
#include <math.h>

#define BATCH 64
#define NTOT  65536
#define DIM   1024
#define CHUNK 256
#define MAX_CHUNKS 320    // NTOT/CHUNK + BATCH
#define NSPLIT 16

// ---------------- device scratch (static, no allocation) ----------------
__device__ float  g_vpart[NSPLIT * BATCH * DIM];
__device__ float  g_v[BATCH * DIM];
__device__ int    g_chunk_seg[MAX_CHUNKS];
__device__ int    g_chunk_start[MAX_CHUNKS];
__device__ int    g_chunk_cnt[MAX_CHUNKS];
__device__ int    g_seg_chunk_start[BATCH];
__device__ int    g_seg_chunk_cnt[BATCH];
__device__ float  g_part_m[MAX_CHUNKS];
__device__ float  g_part_z[MAX_CHUNKS];
__device__ float4 g_part_acc[MAX_CHUNKS * (DIM / 4)];
__device__ int    g_tile_done[NSPLIT];   // split-K arrivals; self-cleaning
__device__ int    g_seg_done[BATCH];     // per-segment chunk arrivals; self-cleaning

// packed f32x2 helpers (sm_103a FFMA2 — PTX-only)
#define FMA2(d, a, b, c) \
    asm("fma.rn.f32x2 %0, %1, %2, %3;" : "=l"(d) : "l"(a), "l"(b), "l"(c))
#define PACK2(out, lo, hi) \
    asm("mov.b64 %0, {%1, %2};" : "=l"(out) : "f"(lo), "f"(hi))

// ============ K1: v-projection (f32x2) + split-K reduce + setup ============
__global__ void k1_vproj_setup(const float* __restrict__ dstate,
                               const float* __restrict__ W,
                               const int* __restrict__ lens_raw) {
    __shared__ unsigned long long dsh2[8][64];   // 16 b's packed into 8 f32x2, 64 h
    int m  = blockIdx.x * 256 + threadIdx.x;
    int b0 = blockIdx.y * 16;
    int h0 = blockIdx.z * 64;

    for (int i = threadIdx.x; i < 8 * 64; i += 256) {
        int p = i >> 6, hh = i & 63;
        float lo = dstate[(b0 + 2 * p)     * DIM + h0 + hh];
        float hi = dstate[(b0 + 2 * p + 1) * DIM + h0 + hh];
        unsigned long long pk; PACK2(pk, lo, hi);
        dsh2[p][hh] = pk;
    }
    __syncthreads();

    unsigned long long acc2[8];
#pragma unroll
    for (int i = 0; i < 8; i++) acc2[i] = 0ull;

#pragma unroll 4
    for (int hh = 0; hh < 64; hh++) {
        float w = W[(size_t)(h0 + hh) * DIM + m];
        unsigned long long w2; PACK2(w2, w, w);
#pragma unroll
        for (int i = 0; i < 8; i++) FMA2(acc2[i], dsh2[i][hh], w2, acc2[i]);
    }

    float* outp = g_vpart + (size_t)blockIdx.z * (BATCH * DIM);
#pragma unroll
    for (int i = 0; i < 8; i++) {
        unsigned long long a = acc2[i];
        outp[(b0 + 2 * i)     * DIM + m] = __int_as_float((int)(a & 0xffffffffull));
        outp[(b0 + 2 * i + 1) * DIM + m] = __int_as_float((int)(a >> 32));
    }

    // ---- last z-split for this (bx,by) tile reduces the 16 partials ----
    __shared__ int s_last;
    __threadfence();
    __syncthreads();
    if (threadIdx.x == 0)
        s_last = (atomicAdd(&g_tile_done[blockIdx.y * 4 + blockIdx.x], 1) == NSPLIT - 1) ? 1 : 0;
    __syncthreads();
    if (s_last) {
        __threadfence();   // acquire: make all splits' writes visible
        for (int i = threadIdx.x; i < 16 * 256; i += 256) {
            int bl = i >> 8, mm = i & 255;
            int b  = blockIdx.y * 16 + bl;
            int mc = blockIdx.x * 256 + mm;
            float s = 0.f;
#pragma unroll
            for (int p = 0; p < NSPLIT; p++)
                s += g_vpart[(size_t)p * BATCH * DIM + b * DIM + mc];
            g_v[b * DIM + mc] = s;
        }
        if (threadIdx.x == 0)
            g_tile_done[blockIdx.y * 4 + blockIdx.x] = 0;   // self-clean for replay
    }

    // ---- setup (chunk table) in block (0,0,0) ----
    if (blockIdx.x == 0 && blockIdx.y == 0 && blockIdx.z == 0) {
        __shared__ int s_len[BATCH], s_noff[BATCH], s_coff[BATCH];
        int b = threadIdx.x;
        const long long* lens64 = (const long long*)lens_raw;
        bool is64 = (lens_raw[1] == 0);   // int64 LE: high word of elem0 is 0
        if (b < BATCH) s_len[b] = is64 ? (int)lens64[b] : lens_raw[b];
        __syncthreads();
        if (b == 0) {
            int noff = 0, coff = 0;
            for (int i = 0; i < BATCH; i++) {
                s_noff[i] = noff; s_coff[i] = coff;
                noff += s_len[i];
                coff += (s_len[i] + CHUNK - 1) / CHUNK;
            }
        }
        __syncthreads();
        if (b < BATCH) {
            int len = s_len[b];
            int nck = (len + CHUNK - 1) / CHUNK;
            int cs  = s_coff[b];
            g_seg_chunk_start[b] = cs;
            g_seg_chunk_cnt[b]   = nck;
            for (int k = 0; k < nck; k++) {
                g_chunk_seg[cs + k]   = b;
                g_chunk_start[cs + k] = s_noff[b] + k * CHUNK;
                int rem = len - k * CHUNK;
                g_chunk_cnt[cs + k]   = rem < CHUNK ? rem : CHUNK;
            }
        }
        __syncthreads();
        int total = s_coff[BATCH - 1] + (s_len[BATCH - 1] + CHUNK - 1) / CHUNK;
        for (int c = total + threadIdx.x; c < MAX_CHUNKS; c += 256) g_chunk_cnt[c] = 0;
    }
}

// ============ K2: one CTA = one chunk, 2-deep pipelined loads + last-arriver combine ============
__global__ void __launch_bounds__(256, 2) k2_phase1(const float* __restrict__ mem,
                                                    float* __restrict__ out) {
    __shared__ float4 s_acc[8][256];   // 32 KB per-warp accumulators
    __shared__ float4 s_v[256];        // 4 KB: segment v row
    __shared__ float  s_m[8], s_z[8];
    __shared__ int    s_last;

    int c   = blockIdx.x;
    int cnt = g_chunk_cnt[c];
    if (cnt == 0) return;
    int seg   = g_chunk_seg[c];
    int start = g_chunk_start[c];
    int warp  = threadIdx.x >> 5;
    int lane  = threadIdx.x & 31;
    int t     = threadIdx.x;

    float m = -INFINITY, z = 0.f;
    float4 acc[8];
#pragma unroll
    for (int j = 0; j < 8; j++) acc[j] = make_float4(0.f, 0.f, 0.f, 0.f);

    auto loadrow = [&](float4* r, int i) {
        const float4* row = (const float4*)(mem + (size_t)(start + i) * DIM);
#pragma unroll
        for (int j = 0; j < 8; j++) r[j] = row[j * 32 + lane];
    };
    auto process = [&](const float4* r) {
        float s0 = 0.f, s1 = 0.f;
#pragma unroll
        for (int j = 0; j < 8; j += 2) {
            float4 v0 = s_v[j * 32 + lane];
            float4 v1 = s_v[(j + 1) * 32 + lane];
            s0 += r[j].x * v0.x + r[j].y * v0.y + r[j].z * v0.z + r[j].w * v0.w;
            s1 += r[j+1].x * v1.x + r[j+1].y * v1.y + r[j+1].z * v1.z + r[j+1].w * v1.w;
        }
        float s = s0 + s1;
#pragma unroll
        for (int o = 16; o > 0; o >>= 1) s += __shfl_xor_sync(0xffffffffu, s, o);

        if (s > m) {
            float sc = __expf(m - s);   // exp(-inf)=0 handles first row
            z = z * sc + 1.f;
#pragma unroll
            for (int j = 0; j < 8; j++) {
                acc[j].x = acc[j].x * sc + r[j].x;
                acc[j].y = acc[j].y * sc + r[j].y;
                acc[j].z = acc[j].z * sc + r[j].z;
                acc[j].w = acc[j].w * sc + r[j].w;
            }
            m = s;
        } else {
            float w8 = __expf(s - m);
            z += w8;
#pragma unroll
            for (int j = 0; j < 8; j++) {
                acc[j].x = fmaf(w8, r[j].x, acc[j].x);
                acc[j].y = fmaf(w8, r[j].y, acc[j].y);
                acc[j].z = fmaf(w8, r[j].z, acc[j].z);
                acc[j].w = fmaf(w8, r[j].w, acc[j].w);
            }
        }
    };

    // preload first row (before barrier: doesn't need v), stage v to shared
    float4 rA[8], rB[8];
    if (warp < cnt) loadrow(rA, warp);
    s_v[t] = ((const float4*)(g_v + seg * DIM))[t];
    __syncthreads();

    // 2-deep software pipeline: next row's 8 LDG.128 issued before processing current
    for (int i = warp; i < cnt; i += 16) {
        int i1 = i + 8;
        if (i1 < cnt) loadrow(rB, i1);
        process(rA);
        if (i1 < cnt) {
            int i2 = i1 + 8;
            if (i2 < cnt) loadrow(rA, i2);
            process(rB);
        }
    }

    // combine 8 warp-local accumulators -> chunk partial
    __syncthreads();   // all reads of s_v done before s_acc aliasing concerns
#pragma unroll
    for (int j = 0; j < 8; j++) s_acc[warp][j * 32 + lane] = acc[j];
    if (lane == 0) { s_m[warp] = m; s_z[warp] = z; }
    __syncthreads();

    float m_b = -INFINITY;
#pragma unroll
    for (int w = 0; w < 8; w++) m_b = fmaxf(m_b, s_m[w]);

    float  z_b = 0.f;
    float4 a   = make_float4(0.f, 0.f, 0.f, 0.f);
#pragma unroll
    for (int w = 0; w < 8; w++) {
        float mw = s_m[w];
        float sc = (mw == -INFINITY) ? 0.f : __expf(mw - m_b);  // idle warp -> 0
        float4 aw = s_acc[w][t];
        a.x = fmaf(sc, aw.x, a.x);
        a.y = fmaf(sc, aw.y, a.y);
        a.z = fmaf(sc, aw.z, a.z);
        a.w = fmaf(sc, aw.w, a.w);
        z_b = fmaf(sc, s_z[w], z_b);
    }
    g_part_acc[c * (DIM / 4) + t] = a;
    if (t == 0) { g_part_m[c] = m_b; g_part_z[c] = z_b; }

    // ---- event-driven last-arriver: final combine for this segment ----
    __threadfence();
    __syncthreads();
    if (t == 0)
        s_last = (atomicAdd(&g_seg_done[seg], 1) == g_seg_chunk_cnt[seg] - 1) ? 1 : 0;
    __syncthreads();
    if (s_last) {
        __threadfence();   // acquire: other chunks' partials now visible
        int cs = g_seg_chunk_start[seg];
        int cc = g_seg_chunk_cnt[seg];

        float m_g = -INFINITY;
        for (int ci = 0; ci < cc; ci++) m_g = fmaxf(m_g, g_part_m[cs + ci]);

        float  zg = 0.f;
        float4 ag = make_float4(0.f, 0.f, 0.f, 0.f);
        for (int ci = 0; ci < cc; ci++) {
            float sc = __expf(g_part_m[cs + ci] - m_g);
            float4 p = g_part_acc[(cs + ci) * (DIM / 4) + t];
            ag.x = fmaf(sc, p.x, ag.x);
            ag.y = fmaf(sc, p.y, ag.y);
            ag.z = fmaf(sc, p.z, ag.z);
            ag.w = fmaf(sc, p.w, ag.w);
            zg = fmaf(sc, g_part_z[cs + ci], zg);
        }
        float inv = 1.f / zg;
        ((float4*)out)[seg * (DIM / 4) + t] =
            make_float4(ag.x * inv, ag.y * inv, ag.z * inv, ag.w * inv);
        if (t == 0) g_seg_done[seg] = 0;   // self-clean for graph replay
    }
}

// ---------------- launch ----------------
extern "C" void kernel_launch(void* const* d_in, const int* in_sizes, int n_in,
                              void* d_out, int out_size) {
    // Identify inputs by element count (ordering-proof):
    //   memory_bank 67108864, decoder_state 65536, W 1048576, lens 64.
    const float* mem    = nullptr;
    const float* dstate = nullptr;
    const float* W      = nullptr;
    const int*   lens   = nullptr;
    for (int i = 0; i < n_in; i++) {
        switch (in_sizes[i]) {
            case 67108864: mem    = (const float*)d_in[i]; break;
            case 65536:    dstate = (const float*)d_in[i]; break;
            case 1048576:  W      = (const float*)d_in[i]; break;
            case 64:       lens   = (const int*)d_in[i];   break;
        }
    }
    float* out = (float*)d_out;

    k1_vproj_setup<<<dim3(4, 4, NSPLIT), 256>>>(dstate, W, lens);
    k2_phase1<<<MAX_CHUNKS, 256>>>(mem, out);
}